// round 1
// baseline (speedup 1.0000x reference)
#include <cuda_runtime.h>

// ---------------- problem constants (fixed shapes per setup_inputs) ----------------
#define BATCH   4
#define NPROP   512
#define M_DIM   (BATCH * NPROP)    // 2048 rows
#define K_DIM   25088              // C*Hp*Wp = 512*49
#define H_DIM   4096
#define NCLS    21
#define NOUT    25                 // 21 cls + 4 reg
#define IMG_MAX 599.0f
#define IOU_THR 0.5f
#define SCORE_THR 0.01f

// ---------------- device scratch (no allocation allowed) ----------------
__device__ float g_x[M_DIM * H_DIM];     // FC1 output, 33.5 MB
__device__ float g_score[M_DIM];         // masked score per proposal
__device__ float g_boxes[M_DIM * 4];     // decoded xywh per proposal

// ---------------- packed f32x2 helpers (Blackwell FFMA2 path) ----------------
__device__ __forceinline__ void fma2(unsigned long long& c, unsigned long long a, unsigned long long b) {
    asm("fma.rn.f32x2 %0, %1, %2, %0;" : "+l"(c) : "l"(a), "l"(b));
}
__device__ __forceinline__ unsigned long long pack2(float lo, float hi) {
    unsigned long long r;
    asm("mov.b64 %0, {%1, %2};" : "=l"(r) : "f"(lo), "f"(hi));
    return r;
}
__device__ __forceinline__ float2 unpack2(unsigned long long v) {
    float2 r;
    asm("mov.b64 {%0, %1}, %2;" : "=f"(r.x), "=f"(r.y) : "l"(v));
    return r;
}

// ---------------- FC1 GEMM: C[2048,4096] = A[2048,25088] @ W^T[25088,4096] + b ----------------
// BM=BN=128, BK=32, 256 threads, 8x8 microtile, f32x2 accumulators.
#define BM 128
#define BN 128
#define BK 32
#define SPAD 4

__global__ __launch_bounds__(256, 2)
void gemm_fc1(const float* __restrict__ A,     // rois flattened [2048][25088]
              const float* __restrict__ W,     // W1 [4096][25088]
              const float* __restrict__ bias)  // b1 [4096]
{
    __shared__ float As[BK][BM + SPAD];
    __shared__ float Bs[BK][BN + SPAD];

    const int tid = threadIdx.x;
    const int bm  = blockIdx.y * BM;
    const int bn  = blockIdx.x * BN;
    const int tx  = tid & 15;          // 0..15
    const int ty  = tid >> 4;          // 0..15
    const int rowBase = ty * 8;
    const int colBase = tx * 8;

    unsigned long long c2[8][4];
    #pragma unroll
    for (int i = 0; i < 8; i++)
        #pragma unroll
        for (int j = 0; j < 4; j++)
            c2[i][j] = 0ULL;

    for (int k0 = 0; k0 < K_DIM; k0 += BK) {
        __syncthreads();   // protect previous compute reads before overwriting smem
        // Each thread loads 4 float4 of A and 4 float4 of W (BM*BK/4 = 1024 vec4 / 256 thr)
        #pragma unroll
        for (int i = 0; i < 4; i++) {
            int idx = tid + i * 256;           // 0..1023
            int r   = idx >> 3;                // 0..127
            int kc  = (idx & 7) << 2;          // 0,4,...,28
            float4 va = *reinterpret_cast<const float4*>(A + (size_t)(bm + r) * K_DIM + k0 + kc);
            As[kc + 0][r] = va.x;
            As[kc + 1][r] = va.y;
            As[kc + 2][r] = va.z;
            As[kc + 3][r] = va.w;
            float4 vb = *reinterpret_cast<const float4*>(W + (size_t)(bn + r) * K_DIM + k0 + kc);
            Bs[kc + 0][r] = vb.x;
            Bs[kc + 1][r] = vb.y;
            Bs[kc + 2][r] = vb.z;
            Bs[kc + 3][r] = vb.w;
        }
        __syncthreads();

        #pragma unroll
        for (int k = 0; k < BK; k++) {
            float4 a0 = *reinterpret_cast<const float4*>(&As[k][rowBase]);
            float4 a1 = *reinterpret_cast<const float4*>(&As[k][rowBase + 4]);
            const unsigned long long* bs64 =
                reinterpret_cast<const unsigned long long*>(&Bs[k][colBase]);
            unsigned long long bb0 = bs64[0];
            unsigned long long bb1 = bs64[1];
            unsigned long long bb2 = bs64[2];
            unsigned long long bb3 = bs64[3];
            float av[8] = {a0.x, a0.y, a0.z, a0.w, a1.x, a1.y, a1.z, a1.w};
            #pragma unroll
            for (int i = 0; i < 8; i++) {
                unsigned long long ai = pack2(av[i], av[i]);
                fma2(c2[i][0], ai, bb0);
                fma2(c2[i][1], ai, bb1);
                fma2(c2[i][2], ai, bb2);
                fma2(c2[i][3], ai, bb3);
            }
        }
    }

    // epilogue: + bias, store
    #pragma unroll
    for (int i = 0; i < 8; i++) {
        int r = bm + rowBase + i;
        float* crow = g_x + (size_t)r * H_DIM + bn + colBase;
        const float* brow = bias + bn + colBase;
        #pragma unroll
        for (int j = 0; j < 4; j++) {
            float2 v = unpack2(c2[i][j]);
            crow[2 * j + 0] = v.x + brow[2 * j + 0];
            crow[2 * j + 1] = v.y + brow[2 * j + 1];
        }
    }
}

// ---------------- heads: cls/reg projections + softmax + argmax + box decode ----------------
__global__ __launch_bounds__(128)
void heads_kernel(const float* __restrict__ Wc, const float* __restrict__ bc,
                  const float* __restrict__ Wr, const float* __restrict__ br,
                  const float* __restrict__ proposals)
{
    const int row = blockIdx.x;      // 0..2047
    const int tid = threadIdx.x;     // 0..127
    const float* xr = g_x + (size_t)row * H_DIM;

    float acc[NOUT];
    #pragma unroll
    for (int c = 0; c < NOUT; c++) acc[c] = 0.f;

    for (int k = tid; k < H_DIM; k += 128) {
        float xv = xr[k];
        #pragma unroll
        for (int c = 0; c < NCLS; c++) acc[c] += xv * Wc[c * H_DIM + k];
        #pragma unroll
        for (int c = 0; c < 4; c++) acc[NCLS + c] += xv * Wr[c * H_DIM + k];
    }
    // warp reduce
    #pragma unroll
    for (int c = 0; c < NOUT; c++)
        #pragma unroll
        for (int o = 16; o > 0; o >>= 1)
            acc[c] += __shfl_xor_sync(0xffffffffu, acc[c], o);

    __shared__ float part[4][NOUT];
    int w = tid >> 5, l = tid & 31;
    if (l == 0) {
        #pragma unroll
        for (int c = 0; c < NOUT; c++) part[w][c] = acc[c];
    }
    __syncthreads();

    if (tid == 0) {
        float cls[NCLS], reg[4];
        #pragma unroll
        for (int c = 0; c < NCLS; c++)
            cls[c] = part[0][c] + part[1][c] + part[2][c] + part[3][c] + bc[c];
        #pragma unroll
        for (int c = 0; c < 4; c++)
            reg[c] = part[0][NCLS + c] + part[1][NCLS + c] + part[2][NCLS + c] + part[3][NCLS + c] + br[c];

        // argmax (first-max like jnp.argmax) + softmax max prob = 1/sum(exp(cls-m))
        float m = cls[0]; int am = 0;
        #pragma unroll
        for (int c = 1; c < NCLS; c++) if (cls[c] > m) { m = cls[c]; am = c; }
        float s = 0.f;
        #pragma unroll
        for (int c = 0; c < NCLS; c++) s += expf(cls[c] - m);
        float score = 1.f / s;
        bool valid = (am != 0) && (score >= SCORE_THR);
        g_score[row] = valid ? score : 0.f;

        float p0 = proposals[row * 4 + 0];
        float p1 = proposals[row * 4 + 1];
        float p2 = proposals[row * 4 + 2];
        float p3 = proposals[row * 4 + 3];
        g_boxes[row * 4 + 0] = p0 + p2 * reg[0];
        g_boxes[row * 4 + 1] = p1 + p3 * reg[1];
        g_boxes[row * 4 + 2] = p2 * expf(reg[2]);
        g_boxes[row * 4 + 3] = p3 * expf(reg[3]);
    }
}

// ---------------- NMS per batch (exact jnp semantics) ----------------
__global__ __launch_bounds__(NPROP)
void nms_kernel(float* __restrict__ out)
{
    const int b   = blockIdx.x;
    const int tid = threadIdx.x;   // 0..511

    __shared__ float sx0[NPROP], sy0[NPROP], sx1[NPROP], sy1[NPROP], sarea[NPROP];
    __shared__ float sscore[NPROP];
    __shared__ int   sidx[NPROP];
    __shared__ int   ssupp[NPROP];

    const int gi = b * NPROP + tid;
    float sc = g_score[gi];
    float bx = g_boxes[gi * 4 + 0];
    float by = g_boxes[gi * 4 + 1];
    float bw = g_boxes[gi * 4 + 2];
    float bh = g_boxes[gi * 4 + 3];
    float x0 = fminf(fmaxf(bx, 0.f), IMG_MAX);
    float y0 = fminf(fmaxf(by, 0.f), IMG_MAX);
    float x1 = fminf(fmaxf(bx + bw - 1.f, 0.f), IMG_MAX);
    float y1 = fminf(fmaxf(by + bh - 1.f, 0.f), IMG_MAX);
    sx0[tid] = x0; sy0[tid] = y0; sx1[tid] = x1; sy1[tid] = y1;
    sarea[tid] = fmaxf(x1 - x0 + 1.f, 0.f) * fmaxf(y1 - y0 + 1.f, 0.f);
    sscore[tid] = sc;
    sidx[tid] = tid;
    ssupp[tid] = 0;
    __syncthreads();

    // bitonic sort: descending score, ascending original index on ties (stable like jnp.argsort(-s))
    for (int k = 2; k <= NPROP; k <<= 1) {
        for (int j = k >> 1; j > 0; j >>= 1) {
            int ixj = tid ^ j;
            if (ixj > tid) {
                float s1 = sscore[tid], s2 = sscore[ixj];
                int   i1 = sidx[tid],   i2 = sidx[ixj];
                bool aBeforeB = (s1 > s2) || (s1 == s2 && i1 < i2);
                bool up = ((tid & k) == 0);
                if (up ? !aBeforeB : aBeforeB) {
                    sscore[tid] = s2; sscore[ixj] = s1;
                    sidx[tid]   = i2; sidx[ixj]   = i1;
                }
            }
            __syncthreads();
        }
    }

    // sequential pivot suppression
    for (int i = 0; i < NPROP; i++) {
        __syncthreads();
        if (ssupp[i] || !(sscore[i] > 0.f)) continue;
        if (tid == i) continue;
        int pi = sidx[i], pj = sidx[tid];
        float ix0 = fmaxf(sx0[pi], sx0[pj]);
        float iy0 = fmaxf(sy0[pi], sy0[pj]);
        float ix1 = fminf(sx1[pi], sx1[pj]);
        float iy1 = fminf(sy1[pi], sy1[pj]);
        float inter = fmaxf(ix1 - ix0 + 1.f, 0.f) * fmaxf(iy1 - iy0 + 1.f, 0.f);
        float iou = inter / (sarea[pi] + sarea[pj] - inter + 1e-9f);
        if (iou > IOU_THR) ssupp[tid] = 1;
    }
    __syncthreads();

    // outputs: [clss_out: B*N floats][bboxes_out: B*N*4 floats]
    bool keep = (ssupp[tid] == 0) && (sscore[tid] > 0.f);
    int orig = sidx[tid];
    int g = b * NPROP + orig;
    float osc = keep ? sscore[tid] : 0.f;
    float obx = keep ? g_boxes[g * 4 + 0] : 0.f;
    float oby = keep ? g_boxes[g * 4 + 1] : 0.f;
    float obw = keep ? g_boxes[g * 4 + 2] : 0.f;
    float obh = keep ? g_boxes[g * 4 + 3] : 0.f;
    out[g] = osc;
    float* bbout = out + (size_t)BATCH * NPROP + (size_t)g * 4;
    bbout[0] = obx;
    bbout[1] = oby;
    bbout[2] = obx + obw - 1.f;
    bbout[3] = oby + obh - 1.f;
}

// ---------------- launch ----------------
extern "C" void kernel_launch(void* const* d_in, const int* in_sizes, int n_in,
                              void* d_out, int out_size)
{
    const float* rois      = (const float*)d_in[0];
    const float* proposals = (const float*)d_in[1];
    const float* W1        = (const float*)d_in[2];
    const float* b1        = (const float*)d_in[3];
    const float* Wc        = (const float*)d_in[4];
    const float* bc        = (const float*)d_in[5];
    const float* Wr        = (const float*)d_in[6];
    const float* br        = (const float*)d_in[7];
    float* out = (float*)d_out;

    dim3 gGemm(H_DIM / BN, M_DIM / BM);   // (32, 16)
    gemm_fc1<<<gGemm, 256>>>(rois, W1, b1);
    heads_kernel<<<M_DIM, 128>>>(Wc, bc, Wr, br, proposals);
    nms_kernel<<<BATCH, NPROP>>>(out);
}

// round 3
// speedup vs baseline: 2.2140x; 2.2140x over previous
#include <cuda_runtime.h>
#include <cuda_bf16.h>
#include <cstdint>

// ---------------- problem constants ----------------
#define BATCH   4
#define NPROP   512
#define M_DIM   (BATCH * NPROP)    // 2048
#define K_DIM   25088              // 512*7*7
#define H_DIM   4096
#define NCLS    21
#define NOUT    25
#define IMG_MAX 599.0f
#define IOU_THR 0.5f
#define SCORE_THR 0.01f

// ---------------- GEMM tiling ----------------
#define STAGES   3
#define BK       32
#define ITERS    (K_DIM / BK)      // 784
#define ROW_E    40                // padded row length in bf16 (80B) — conflict-free for ldmatrix
#define MAT_B    (128 * ROW_E * 2) // 10240 B per 128x32 tile
#define STAGE_B  (4 * MAT_B)       // Ahi, Alo, Whi, Wlo
#define SMEM_DYN (STAGES * STAGE_B)

// ---------------- device scratch ----------------
__device__ float g_x[(size_t)M_DIM * H_DIM];
__device__ float g_score[M_DIM];
__device__ float g_boxes[M_DIM * 4];
__device__ __nv_bfloat16 g_Ahi[(size_t)M_DIM * K_DIM];
__device__ __nv_bfloat16 g_Alo[(size_t)M_DIM * K_DIM];
__device__ __nv_bfloat16 g_Whi[(size_t)H_DIM * K_DIM];
__device__ __nv_bfloat16 g_Wlo[(size_t)H_DIM * K_DIM];

// ---------------- PTX helpers (baseline ISA only — no 'a'-suffix features) ----------------
static __device__ __forceinline__ uint32_t smem_u32(const void* p) {
    return (uint32_t)__cvta_generic_to_shared(p);
}
static __device__ __forceinline__ void cp16(uint32_t dst, const void* src) {
    asm volatile("cp.async.cg.shared.global [%0], [%1], 16;" :: "r"(dst), "l"(src) : "memory");
}
static __device__ __forceinline__ void ldm_x4(uint32_t* r, uint32_t addr) {
    asm volatile("ldmatrix.sync.aligned.m8n8.x4.shared.b16 {%0,%1,%2,%3}, [%4];"
                 : "=r"(r[0]), "=r"(r[1]), "=r"(r[2]), "=r"(r[3]) : "r"(addr));
}
static __device__ __forceinline__ void mma_bf16(float* d, const uint32_t* a, const uint32_t* b) {
    asm volatile("mma.sync.aligned.m16n8k16.row.col.f32.bf16.bf16.f32 "
                 "{%0,%1,%2,%3}, {%4,%5,%6,%7}, {%8,%9}, {%0,%1,%2,%3};"
                 : "+f"(d[0]), "+f"(d[1]), "+f"(d[2]), "+f"(d[3])
                 : "r"(a[0]), "r"(a[1]), "r"(a[2]), "r"(a[3]), "r"(b[0]), "r"(b[1]));
}

// ---------------- prep: fp32 -> bf16 hi/lo, row-major ----------------
static __device__ __forceinline__ void prep_store(const float* src, __nv_bfloat16* dhi, __nv_bfloat16* dlo,
                                                  size_t chunk_id) {
    size_t e0 = chunk_id * 8;   // 8 consecutive elements of a row (K_DIM % 8 == 0)
    const float4* p = reinterpret_cast<const float4*>(src + e0);
    float4 v0 = p[0], v1 = p[1];
    float f[8] = {v0.x, v0.y, v0.z, v0.w, v1.x, v1.y, v1.z, v1.w};
    uint32_t hi[4], lo[4];
    #pragma unroll
    for (int j = 0; j < 4; j++) {
        __nv_bfloat16 h0 = __float2bfloat16_rn(f[2 * j]);
        __nv_bfloat16 h1 = __float2bfloat16_rn(f[2 * j + 1]);
        __nv_bfloat16 l0 = __float2bfloat16_rn(f[2 * j]     - __bfloat162float(h0));
        __nv_bfloat16 l1 = __float2bfloat16_rn(f[2 * j + 1] - __bfloat162float(h1));
        hi[j] = (uint32_t)__bfloat16_as_ushort(h0) | ((uint32_t)__bfloat16_as_ushort(h1) << 16);
        lo[j] = (uint32_t)__bfloat16_as_ushort(l0) | ((uint32_t)__bfloat16_as_ushort(l1) << 16);
    }
    *reinterpret_cast<uint4*>(dhi + e0) = make_uint4(hi[0], hi[1], hi[2], hi[3]);
    *reinterpret_cast<uint4*>(dlo + e0) = make_uint4(lo[0], lo[1], lo[2], lo[3]);
}
__global__ void prep_A_kernel(const float* __restrict__ src) {
    prep_store(src, g_Ahi, g_Alo, (size_t)blockIdx.x * 256 + threadIdx.x);
}
__global__ void prep_W_kernel(const float* __restrict__ src) {
    prep_store(src, g_Whi, g_Wlo, (size_t)blockIdx.x * 256 + threadIdx.x);
}

// ---------------- stage loader ----------------
static __device__ __forceinline__ void load_stage(uint32_t sbase, int tid, int slot, int kt, int bm, int bn) {
    uint32_t sd = sbase + (uint32_t)slot * STAGE_B;
    int k0 = kt * BK;
    #pragma unroll
    for (int t = 0; t < 8; t++) {
        int c   = tid + t * 256;       // 0..2047 (warp-uniform matrix selection)
        int mat = c >> 9;              // 0:Ahi 1:Alo 2:Whi 3:Wlo
        int idx = c & 511;
        int row = idx >> 2;
        int ck  = idx & 3;
        const __nv_bfloat16* src;
        int grow;
        if (mat == 0)      { src = g_Ahi; grow = bm + row; }
        else if (mat == 1) { src = g_Alo; grow = bm + row; }
        else if (mat == 2) { src = g_Whi; grow = bn + row; }
        else               { src = g_Wlo; grow = bn + row; }
        cp16(sd + (uint32_t)mat * MAT_B + (uint32_t)(row * (ROW_E * 2) + ck * 16),
             src + (size_t)grow * K_DIM + k0 + ck * 8);
    }
}

// ---------------- GEMM: g_x[2048,4096] = A @ W1^T + b1 via mma.sync bf16 3-term split ----------------
__global__ __launch_bounds__(256, 1)
void gemm_mma(const float* __restrict__ bias)
{
    extern __shared__ char smem[];
    const int tid    = threadIdx.x;
    const int lane   = tid & 31;
    const int wid    = tid >> 5;
    const int warp_m = wid & 3;    // 4 groups of 32 rows
    const int warp_n = wid >> 2;   // 2 groups of 64 cols
    const int bm = blockIdx.y * 128;
    const int bn = blockIdx.x * 128;
    const uint32_t sbase = smem_u32(smem);

    float acc[2][8][4];
    #pragma unroll
    for (int mt = 0; mt < 2; mt++)
        #pragma unroll
        for (int nt = 0; nt < 8; nt++)
            #pragma unroll
            for (int j = 0; j < 4; j++)
                acc[mt][nt][j] = 0.f;

    // prologue: preload STAGES-1 stages
    #pragma unroll
    for (int s = 0; s < STAGES - 1; s++) {
        load_stage(sbase, tid, s, s, bm, bn);
        asm volatile("cp.async.commit_group;" ::: "memory");
    }

    // precomputed fragment smem offsets
    const uint32_t a_off0 = (uint32_t)((warp_m * 32 + (lane & 15)) * (ROW_E * 2) + ((lane >> 4) * 8) * 2);
    const uint32_t b_row  = (uint32_t)(warp_n * 64 + ((lane & 7) + ((lane >> 4) << 3)));
    const uint32_t b_off0 = b_row * (ROW_E * 2) + ((((lane >> 3) & 1) << 3)) * 2;

    for (int it = 0; it < ITERS; it++) {
        asm volatile("cp.async.wait_group %0;" :: "n"(STAGES - 2) : "memory");
        __syncthreads();

        int nk = it + STAGES - 1;
        if (nk < ITERS) load_stage(sbase, tid, nk % STAGES, nk, bm, bn);
        asm volatile("cp.async.commit_group;" ::: "memory");

        const uint32_t s0   = sbase + (uint32_t)(it % STAGES) * STAGE_B;
        const uint32_t sAhi = s0;
        const uint32_t sAlo = s0 + MAT_B;
        const uint32_t sWhi = s0 + 2 * MAT_B;
        const uint32_t sWlo = s0 + 3 * MAT_B;

        #pragma unroll
        for (int ks = 0; ks < 2; ks++) {
            uint32_t ah[2][4], al[2][4], bh[8][2], bl[8][2];
            uint32_t aoff = a_off0 + (uint32_t)(ks * 32);   // ks*16 elems * 2B
            #pragma unroll
            for (int mt = 0; mt < 2; mt++) {
                ldm_x4(ah[mt], sAhi + aoff + (uint32_t)(mt * 16 * ROW_E * 2));
                ldm_x4(al[mt], sAlo + aoff + (uint32_t)(mt * 16 * ROW_E * 2));
            }
            uint32_t boff = b_off0 + (uint32_t)(ks * 32);
            #pragma unroll
            for (int nt2 = 0; nt2 < 4; nt2++) {
                uint32_t r[4];
                ldm_x4(r, sWhi + boff + (uint32_t)(nt2 * 16 * ROW_E * 2));
                bh[nt2 * 2][0] = r[0]; bh[nt2 * 2][1] = r[1];
                bh[nt2 * 2 + 1][0] = r[2]; bh[nt2 * 2 + 1][1] = r[3];
                ldm_x4(r, sWlo + boff + (uint32_t)(nt2 * 16 * ROW_E * 2));
                bl[nt2 * 2][0] = r[0]; bl[nt2 * 2][1] = r[1];
                bl[nt2 * 2 + 1][0] = r[2]; bl[nt2 * 2 + 1][1] = r[3];
            }
            #pragma unroll
            for (int mt = 0; mt < 2; mt++)
                #pragma unroll
                for (int nt = 0; nt < 8; nt++) {
                    mma_bf16(acc[mt][nt], ah[mt], bh[nt]);
                    mma_bf16(acc[mt][nt], ah[mt], bl[nt]);
                    mma_bf16(acc[mt][nt], al[mt], bh[nt]);
                }
        }
    }

    // epilogue: acc (+bias) -> g_x
    #pragma unroll
    for (int mt = 0; mt < 2; mt++) {
        int r0 = bm + warp_m * 32 + mt * 16 + (lane >> 2);
        #pragma unroll
        for (int nt = 0; nt < 8; nt++) {
            int col = bn + warp_n * 64 + nt * 8 + (lane & 3) * 2;
            float b0 = __ldg(bias + col), b1 = __ldg(bias + col + 1);
            float* p0 = g_x + (size_t)r0 * H_DIM + col;
            float* p1 = g_x + (size_t)(r0 + 8) * H_DIM + col;
            p0[0] = acc[mt][nt][0] + b0;
            p0[1] = acc[mt][nt][1] + b1;
            p1[0] = acc[mt][nt][2] + b0;
            p1[1] = acc[mt][nt][3] + b1;
        }
    }
}

// ---------------- heads: cls/reg + softmax + argmax + box decode ----------------
__global__ __launch_bounds__(128)
void heads_kernel(const float* __restrict__ Wc, const float* __restrict__ bc,
                  const float* __restrict__ Wr, const float* __restrict__ br,
                  const float* __restrict__ proposals)
{
    const int row = blockIdx.x;
    const int tid = threadIdx.x;
    const float* xr = g_x + (size_t)row * H_DIM;

    float acc[NOUT];
    #pragma unroll
    for (int c = 0; c < NOUT; c++) acc[c] = 0.f;

    for (int k = tid; k < H_DIM; k += 128) {
        float xv = xr[k];
        #pragma unroll
        for (int c = 0; c < NCLS; c++) acc[c] += xv * Wc[c * H_DIM + k];
        #pragma unroll
        for (int c = 0; c < 4; c++) acc[NCLS + c] += xv * Wr[c * H_DIM + k];
    }
    #pragma unroll
    for (int c = 0; c < NOUT; c++)
        #pragma unroll
        for (int o = 16; o > 0; o >>= 1)
            acc[c] += __shfl_xor_sync(0xffffffffu, acc[c], o);

    __shared__ float part[4][NOUT];
    int w = tid >> 5, l = tid & 31;
    if (l == 0) {
        #pragma unroll
        for (int c = 0; c < NOUT; c++) part[w][c] = acc[c];
    }
    __syncthreads();

    if (tid == 0) {
        float cls[NCLS], reg[4];
        #pragma unroll
        for (int c = 0; c < NCLS; c++)
            cls[c] = part[0][c] + part[1][c] + part[2][c] + part[3][c] + bc[c];
        #pragma unroll
        for (int c = 0; c < 4; c++)
            reg[c] = part[0][NCLS + c] + part[1][NCLS + c] + part[2][NCLS + c] + part[3][NCLS + c] + br[c];

        float m = cls[0]; int am = 0;
        #pragma unroll
        for (int c = 1; c < NCLS; c++) if (cls[c] > m) { m = cls[c]; am = c; }
        float s = 0.f;
        #pragma unroll
        for (int c = 0; c < NCLS; c++) s += expf(cls[c] - m);
        float score = 1.f / s;
        bool valid = (am != 0) && (score >= SCORE_THR);
        g_score[row] = valid ? score : 0.f;

        float p0 = proposals[row * 4 + 0];
        float p1 = proposals[row * 4 + 1];
        float p2 = proposals[row * 4 + 2];
        float p3 = proposals[row * 4 + 3];
        g_boxes[row * 4 + 0] = p0 + p2 * reg[0];
        g_boxes[row * 4 + 1] = p1 + p3 * reg[1];
        g_boxes[row * 4 + 2] = p2 * expf(reg[2]);
        g_boxes[row * 4 + 3] = p3 * expf(reg[3]);
    }
}

// ---------------- NMS (exact jnp semantics) ----------------
__global__ __launch_bounds__(NPROP)
void nms_kernel(float* __restrict__ out)
{
    const int b   = blockIdx.x;
    const int tid = threadIdx.x;

    __shared__ float sx0[NPROP], sy0[NPROP], sx1[NPROP], sy1[NPROP], sarea[NPROP];
    __shared__ float sscore[NPROP];
    __shared__ int   sidx[NPROP];
    __shared__ int   ssupp[NPROP];

    const int gi = b * NPROP + tid;
    float sc = g_score[gi];
    float bx = g_boxes[gi * 4 + 0];
    float by = g_boxes[gi * 4 + 1];
    float bw = g_boxes[gi * 4 + 2];
    float bh = g_boxes[gi * 4 + 3];
    float x0 = fminf(fmaxf(bx, 0.f), IMG_MAX);
    float y0 = fminf(fmaxf(by, 0.f), IMG_MAX);
    float x1 = fminf(fmaxf(bx + bw - 1.f, 0.f), IMG_MAX);
    float y1 = fminf(fmaxf(by + bh - 1.f, 0.f), IMG_MAX);
    sx0[tid] = x0; sy0[tid] = y0; sx1[tid] = x1; sy1[tid] = y1;
    sarea[tid] = fmaxf(x1 - x0 + 1.f, 0.f) * fmaxf(y1 - y0 + 1.f, 0.f);
    sscore[tid] = sc;
    sidx[tid] = tid;
    ssupp[tid] = 0;
    __syncthreads();

    for (int k = 2; k <= NPROP; k <<= 1) {
        for (int j = k >> 1; j > 0; j >>= 1) {
            int ixj = tid ^ j;
            if (ixj > tid) {
                float s1 = sscore[tid], s2 = sscore[ixj];
                int   i1 = sidx[tid],   i2 = sidx[ixj];
                bool aBeforeB = (s1 > s2) || (s1 == s2 && i1 < i2);
                bool up = ((tid & k) == 0);
                if (up ? !aBeforeB : aBeforeB) {
                    sscore[tid] = s2; sscore[ixj] = s1;
                    sidx[tid]   = i2; sidx[ixj]   = i1;
                }
            }
            __syncthreads();
        }
    }

    for (int i = 0; i < NPROP; i++) {
        __syncthreads();
        if (ssupp[i] || !(sscore[i] > 0.f)) continue;
        if (tid == i) continue;
        int pi = sidx[i], pj = sidx[tid];
        float ix0 = fmaxf(sx0[pi], sx0[pj]);
        float iy0 = fmaxf(sy0[pi], sy0[pj]);
        float ix1 = fminf(sx1[pi], sx1[pj]);
        float iy1 = fminf(sy1[pi], sy1[pj]);
        float inter = fmaxf(ix1 - ix0 + 1.f, 0.f) * fmaxf(iy1 - iy0 + 1.f, 0.f);
        float iou = inter / (sarea[pi] + sarea[pj] - inter + 1e-9f);
        if (iou > IOU_THR) ssupp[tid] = 1;
    }
    __syncthreads();

    bool keep = (ssupp[tid] == 0) && (sscore[tid] > 0.f);
    int orig = sidx[tid];
    int g = b * NPROP + orig;
    float osc = keep ? sscore[tid] : 0.f;
    float obx = keep ? g_boxes[g * 4 + 0] : 0.f;
    float oby = keep ? g_boxes[g * 4 + 1] : 0.f;
    float obw = keep ? g_boxes[g * 4 + 2] : 0.f;
    float obh = keep ? g_boxes[g * 4 + 3] : 0.f;
    out[g] = osc;
    float* bbout = out + (size_t)BATCH * NPROP + (size_t)g * 4;
    bbout[0] = obx;
    bbout[1] = oby;
    bbout[2] = obx + obw - 1.f;
    bbout[3] = oby + obh - 1.f;
}

// ---------------- launch ----------------
extern "C" void kernel_launch(void* const* d_in, const int* in_sizes, int n_in,
                              void* d_out, int out_size)
{
    const float* rois      = (const float*)d_in[0];
    const float* proposals = (const float*)d_in[1];
    const float* W1        = (const float*)d_in[2];
    const float* b1        = (const float*)d_in[3];
    const float* Wc        = (const float*)d_in[4];
    const float* bc        = (const float*)d_in[5];
    const float* Wr        = (const float*)d_in[6];
    const float* br        = (const float*)d_in[7];
    float* out = (float*)d_out;

    cudaFuncSetAttribute(gemm_mma, cudaFuncAttributeMaxDynamicSharedMemorySize, SMEM_DYN);

    prep_A_kernel<<<(M_DIM * (K_DIM / 8)) / 256, 256>>>(rois);
    prep_W_kernel<<<(H_DIM * (K_DIM / 8)) / 256, 256>>>(W1);
    gemm_mma<<<dim3(H_DIM / 128, M_DIM / 128), 256, SMEM_DYN>>>(b1);
    heads_kernel<<<M_DIM, 128>>>(Wc, bc, Wr, br, proposals);
    nms_kernel<<<BATCH, NPROP>>>(out);
}

// round 4
// speedup vs baseline: 14.9190x; 6.7384x over previous
#include <cuda_runtime.h>
#include <cstdint>
#include <math.h>

// ---------------- problem constants ----------------
#define BATCH   4
#define NPROP   512
#define M_DIM   (BATCH * NPROP)    // 2048
#define D_DIM   25088              // 512*7*7
#define H_DIM   4096
#define NCLS    21
#define CPAD    32                 // 25 outputs padded to 32
#define IMG_MAX 599.0f
#define IOU_THR 0.5f
#define SCORE_THR 0.01f
#define KPARTS  16                 // K-split for logits GEMM (25088/16 = 1568)
#define KPART_D 1568

// ---------------- device scratch ----------------
__device__ float g_Wcr1[(size_t)D_DIM * CPAD];          // [d][c] fused weights
__device__ float g_bias[CPAD];                          // fused bias
__device__ float g_part[(size_t)KPARTS * M_DIM * CPAD]; // logits partials
__device__ float g_score[M_DIM];
__device__ float g_boxes[M_DIM * 4];

// ---------------- packed f32x2 helpers ----------------
__device__ __forceinline__ void fma2(unsigned long long& c, unsigned long long a, unsigned long long b) {
    asm("fma.rn.f32x2 %0, %1, %2, %0;" : "+l"(c) : "l"(a), "l"(b));
}
__device__ __forceinline__ unsigned long long pack2(float lo, float hi) {
    unsigned long long r;
    asm("mov.b64 %0, {%1, %2};" : "=l"(r) : "f"(lo), "f"(hi));
    return r;
}
__device__ __forceinline__ float2 unpack2(unsigned long long v) {
    float2 r;
    asm("mov.b64 {%0, %1}, %2;" : "=f"(r.x), "=f"(r.y) : "l"(v));
    return r;
}

// ============ kernel A: Wcr1[d][c] = sum_h Wcr[c][h] * W1[h][d] ============
// M=32 (c, 25 real), N-tile=128 (d), K=4096 (h), BK=32. 196 blocks, 256 threads.
__global__ __launch_bounds__(256)
void fuse_w(const float* __restrict__ Wc, const float* __restrict__ Wr,
            const float* __restrict__ W1)
{
    __shared__ float As[32][33];    // [c][h]  (stride 33: conflict-free scalar access)
    __shared__ float Bs[32][132];   // [h][d]  (stride 132: 16B-aligned float4 rows)

    const int tid = threadIdx.x;
    const int d0  = blockIdx.x * 128;
    const int tx  = tid & 31;      // d-group (4 d each)
    const int ty  = tid >> 5;      // c-group (4 c each), constant per warp

    unsigned long long acc2[4][2];
    #pragma unroll
    for (int i = 0; i < 4; i++) { acc2[i][0] = 0ULL; acc2[i][1] = 0ULL; }

    for (int h0 = 0; h0 < H_DIM; h0 += 32) {
        __syncthreads();
        // load Wcr slice: c = tid>>3 (0..31), hq = tid&7 (4 h each)
        {
            int c = tid >> 3, hq = tid & 7;
            float4 v;
            if (c < NCLS)       v = *reinterpret_cast<const float4*>(Wc + (size_t)c * H_DIM + h0 + hq * 4);
            else if (c < 25)    v = *reinterpret_cast<const float4*>(Wr + (size_t)(c - NCLS) * H_DIM + h0 + hq * 4);
            else                v = make_float4(0.f, 0.f, 0.f, 0.f);
            As[c][4 * hq + 0] = v.x; As[c][4 * hq + 1] = v.y;
            As[c][4 * hq + 2] = v.z; As[c][4 * hq + 3] = v.w;
        }
        // load W1 tile: 4 float4 per thread
        #pragma unroll
        for (int i = 0; i < 4; i++) {
            int f  = tid + i * 256;
            int hk = f >> 5, dq = f & 31;
            float4 v = *reinterpret_cast<const float4*>(W1 + (size_t)(h0 + hk) * D_DIM + d0 + 4 * dq);
            *reinterpret_cast<float4*>(&Bs[hk][4 * dq]) = v;
        }
        __syncthreads();

        #pragma unroll
        for (int k = 0; k < 32; k++) {
            float4 b = *reinterpret_cast<const float4*>(&Bs[k][4 * tx]);
            unsigned long long b01 = pack2(b.x, b.y);
            unsigned long long b23 = pack2(b.z, b.w);
            #pragma unroll
            for (int i = 0; i < 4; i++) {
                float a = As[4 * ty + i][k];
                unsigned long long as = pack2(a, a);
                fma2(acc2[i][0], as, b01);
                fma2(acc2[i][1], as, b23);
            }
        }
    }

    // write g_Wcr1[d][c]
    #pragma unroll
    for (int i = 0; i < 4; i++) {
        int c = 4 * ty + i;
        float2 p0 = unpack2(acc2[i][0]);
        float2 p1 = unpack2(acc2[i][1]);
        g_Wcr1[(size_t)(d0 + 4 * tx + 0) * CPAD + c] = p0.x;
        g_Wcr1[(size_t)(d0 + 4 * tx + 1) * CPAD + c] = p0.y;
        g_Wcr1[(size_t)(d0 + 4 * tx + 2) * CPAD + c] = p1.x;
        g_Wcr1[(size_t)(d0 + 4 * tx + 3) * CPAD + c] = p1.y;
    }
}

// ============ bias: g_bias[c] = bcr[c] + sum_h Wcr[c][h]*b1[h] ============
__global__ __launch_bounds__(256)
void bias_kernel(const float* __restrict__ Wc, const float* __restrict__ bc,
                 const float* __restrict__ Wr, const float* __restrict__ br,
                 const float* __restrict__ b1)
{
    const int c   = blockIdx.x;   // 0..31
    const int tid = threadIdx.x;
    float s = 0.f;
    if (c < 25) {
        const float* w = (c < NCLS) ? (Wc + (size_t)c * H_DIM) : (Wr + (size_t)(c - NCLS) * H_DIM);
        for (int h = tid; h < H_DIM; h += 256) s += w[h] * b1[h];
    }
    #pragma unroll
    for (int o = 16; o > 0; o >>= 1) s += __shfl_xor_sync(0xffffffffu, s, o);
    __shared__ float part[8];
    if ((tid & 31) == 0) part[tid >> 5] = s;
    __syncthreads();
    if (tid == 0) {
        float t = 0.f;
        #pragma unroll
        for (int w = 0; w < 8; w++) t += part[w];
        float base = (c < NCLS) ? bc[c] : (c < 25 ? br[c - NCLS] : 0.f);
        g_bias[c] = (c < 25) ? (t + base) : 0.f;
    }
}

// ============ kernel B: partials[kp][row][c] = sum_{d in part} feats[row][d]*Wcr1[d][c] ============
// M-tile=128 rows, N=32, K-part=1568 (49 x BK=32). grid (16 row-tiles, 16 k-parts), 256 threads.
__global__ __launch_bounds__(256)
void gemm_logits(const float* __restrict__ feats)
{
    __shared__ float As[128][33];   // [row][k]
    __shared__ float Bs[32][36];    // [k][c]

    const int tid = threadIdx.x;
    const int r0  = blockIdx.x * 128;
    const int kp  = blockIdx.y;
    const int dbase = kp * KPART_D;
    const int tx  = tid & 7;        // c-group (4 c)
    const int ty  = tid >> 3;       // row-group (4 rows)

    unsigned long long acc2[4][2];
    #pragma unroll
    for (int i = 0; i < 4; i++) { acc2[i][0] = 0ULL; acc2[i][1] = 0ULL; }

    for (int it = 0; it < KPART_D / 32; it++) {
        int d0 = dbase + it * 32;
        __syncthreads();
        // load feats tile: 4 float4/thread, transposed-scalar store into As[row][k]
        #pragma unroll
        for (int i = 0; i < 4; i++) {
            int f = tid + i * 256;          // 0..1023
            int r = f >> 3, dq = f & 7;
            float4 v = *reinterpret_cast<const float4*>(feats + (size_t)(r0 + r) * D_DIM + d0 + 4 * dq);
            As[r][4 * dq + 0] = v.x; As[r][4 * dq + 1] = v.y;
            As[r][4 * dq + 2] = v.z; As[r][4 * dq + 3] = v.w;
        }
        // load Wcr1 tile: 1 float4/thread
        {
            int k = tid >> 3, cq = tid & 7;
            float4 v = *reinterpret_cast<const float4*>(g_Wcr1 + (size_t)(d0 + k) * CPAD + 4 * cq);
            *reinterpret_cast<float4*>(&Bs[k][4 * cq]) = v;
        }
        __syncthreads();

        #pragma unroll
        for (int k = 0; k < 32; k++) {
            float4 b = *reinterpret_cast<const float4*>(&Bs[k][4 * tx]);
            unsigned long long b01 = pack2(b.x, b.y);
            unsigned long long b23 = pack2(b.z, b.w);
            #pragma unroll
            for (int i = 0; i < 4; i++) {
                float a = As[4 * ty + i][k];
                unsigned long long as = pack2(a, a);
                fma2(acc2[i][0], as, b01);
                fma2(acc2[i][1], as, b23);
            }
        }
    }

    // write partials (float4 per row)
    #pragma unroll
    for (int i = 0; i < 4; i++) {
        int row = r0 + 4 * ty + i;
        float2 p0 = unpack2(acc2[i][0]);
        float2 p1 = unpack2(acc2[i][1]);
        float4 v = make_float4(p0.x, p0.y, p1.x, p1.y);
        *reinterpret_cast<float4*>(g_part + ((size_t)kp * M_DIM + row) * CPAD + 4 * tx) = v;
    }
}

// ============ decode: reduce partials + softmax/argmax + box decode ============
__global__ __launch_bounds__(32)
void decode_kernel(const float* __restrict__ proposals)
{
    const int row = blockIdx.x;    // 0..2047
    const int c   = threadIdx.x;   // 0..31

    float logit = g_bias[c];
    #pragma unroll
    for (int kp = 0; kp < KPARTS; kp++)
        logit += g_part[((size_t)kp * M_DIM + row) * CPAD + c];

    float v  = (c < NCLS) ? logit : -INFINITY;
    float m  = v;
    int   am = c;
    #pragma unroll
    for (int o = 16; o > 0; o >>= 1) {
        float mo = __shfl_xor_sync(0xffffffffu, m, o);
        int   ao = __shfl_xor_sync(0xffffffffu, am, o);
        if (mo > m || (mo == m && ao < am)) { m = mo; am = ao; }
    }
    float e = (c < NCLS) ? expf(v - m) : 0.f;
    #pragma unroll
    for (int o = 16; o > 0; o >>= 1) e += __shfl_xor_sync(0xffffffffu, e, o);

    float r0v = __shfl_sync(0xffffffffu, logit, 21);
    float r1v = __shfl_sync(0xffffffffu, logit, 22);
    float r2v = __shfl_sync(0xffffffffu, logit, 23);
    float r3v = __shfl_sync(0xffffffffu, logit, 24);

    if (c == 0) {
        float score = 1.f / e;
        bool valid = (am != 0) && (score >= SCORE_THR);
        g_score[row] = valid ? score : 0.f;
        float p0 = proposals[row * 4 + 0];
        float p1 = proposals[row * 4 + 1];
        float p2 = proposals[row * 4 + 2];
        float p3 = proposals[row * 4 + 3];
        g_boxes[row * 4 + 0] = p0 + p2 * r0v;
        g_boxes[row * 4 + 1] = p1 + p3 * r1v;
        g_boxes[row * 4 + 2] = p2 * expf(r2v);
        g_boxes[row * 4 + 3] = p3 * expf(r3v);
    }
}

// ---------------- NMS (exact jnp semantics, unchanged from round 3) ----------------
__global__ __launch_bounds__(NPROP)
void nms_kernel(float* __restrict__ out)
{
    const int b   = blockIdx.x;
    const int tid = threadIdx.x;

    __shared__ float sx0[NPROP], sy0[NPROP], sx1[NPROP], sy1[NPROP], sarea[NPROP];
    __shared__ float sscore[NPROP];
    __shared__ int   sidx[NPROP];
    __shared__ int   ssupp[NPROP];

    const int gi = b * NPROP + tid;
    float sc = g_score[gi];
    float bx = g_boxes[gi * 4 + 0];
    float by = g_boxes[gi * 4 + 1];
    float bw = g_boxes[gi * 4 + 2];
    float bh = g_boxes[gi * 4 + 3];
    float x0 = fminf(fmaxf(bx, 0.f), IMG_MAX);
    float y0 = fminf(fmaxf(by, 0.f), IMG_MAX);
    float x1 = fminf(fmaxf(bx + bw - 1.f, 0.f), IMG_MAX);
    float y1 = fminf(fmaxf(by + bh - 1.f, 0.f), IMG_MAX);
    sx0[tid] = x0; sy0[tid] = y0; sx1[tid] = x1; sy1[tid] = y1;
    sarea[tid] = fmaxf(x1 - x0 + 1.f, 0.f) * fmaxf(y1 - y0 + 1.f, 0.f);
    sscore[tid] = sc;
    sidx[tid] = tid;
    ssupp[tid] = 0;
    __syncthreads();

    for (int k = 2; k <= NPROP; k <<= 1) {
        for (int j = k >> 1; j > 0; j >>= 1) {
            int ixj = tid ^ j;
            if (ixj > tid) {
                float s1 = sscore[tid], s2 = sscore[ixj];
                int   i1 = sidx[tid],   i2 = sidx[ixj];
                bool aBeforeB = (s1 > s2) || (s1 == s2 && i1 < i2);
                bool up = ((tid & k) == 0);
                if (up ? !aBeforeB : aBeforeB) {
                    sscore[tid] = s2; sscore[ixj] = s1;
                    sidx[tid]   = i2; sidx[ixj]   = i1;
                }
            }
            __syncthreads();
        }
    }

    for (int i = 0; i < NPROP; i++) {
        __syncthreads();
        if (ssupp[i] || !(sscore[i] > 0.f)) continue;
        if (tid == i) continue;
        int pi = sidx[i], pj = sidx[tid];
        float ix0 = fmaxf(sx0[pi], sx0[pj]);
        float iy0 = fmaxf(sy0[pi], sy0[pj]);
        float ix1 = fminf(sx1[pi], sx1[pj]);
        float iy1 = fminf(sy1[pi], sy1[pj]);
        float inter = fmaxf(ix1 - ix0 + 1.f, 0.f) * fmaxf(iy1 - iy0 + 1.f, 0.f);
        float iou = inter / (sarea[pi] + sarea[pj] - inter + 1e-9f);
        if (iou > IOU_THR) ssupp[tid] = 1;
    }
    __syncthreads();

    bool keep = (ssupp[tid] == 0) && (sscore[tid] > 0.f);
    int orig = sidx[tid];
    int g = b * NPROP + orig;
    float osc = keep ? sscore[tid] : 0.f;
    float obx = keep ? g_boxes[g * 4 + 0] : 0.f;
    float oby = keep ? g_boxes[g * 4 + 1] : 0.f;
    float obw = keep ? g_boxes[g * 4 + 2] : 0.f;
    float obh = keep ? g_boxes[g * 4 + 3] : 0.f;
    out[g] = osc;
    float* bbout = out + (size_t)BATCH * NPROP + (size_t)g * 4;
    bbout[0] = obx;
    bbout[1] = oby;
    bbout[2] = obx + obw - 1.f;
    bbout[3] = oby + obh - 1.f;
}

// ---------------- launch ----------------
extern "C" void kernel_launch(void* const* d_in, const int* in_sizes, int n_in,
                              void* d_out, int out_size)
{
    const float* rois      = (const float*)d_in[0];   // [2048][25088]
    const float* proposals = (const float*)d_in[1];
    const float* W1        = (const float*)d_in[2];
    const float* b1        = (const float*)d_in[3];
    const float* Wc        = (const float*)d_in[4];
    const float* bc        = (const float*)d_in[5];
    const float* Wr        = (const float*)d_in[6];
    const float* br        = (const float*)d_in[7];
    float* out = (float*)d_out;

    fuse_w<<<D_DIM / 128, 256>>>(Wc, Wr, W1);                       // 196 blocks
    bias_kernel<<<CPAD, 256>>>(Wc, bc, Wr, br, b1);                 // 32 blocks
    gemm_logits<<<dim3(M_DIM / 128, KPARTS), 256>>>(rois);          // 16x16 blocks
    decode_kernel<<<M_DIM, 32>>>(proposals);
    nms_kernel<<<BATCH, NPROP>>>(out);
}

// round 5
// speedup vs baseline: 22.1755x; 1.4864x over previous
#include <cuda_runtime.h>
#include <cstdint>
#include <math.h>

// ---------------- problem constants ----------------
#define BATCH   4
#define NPROP   512
#define M_DIM   (BATCH * NPROP)    // 2048
#define D_DIM   25088              // 512*7*7
#define H_DIM   4096
#define NCLS    21
#define CPAD    32
#define IMG_MAX 599.0f
#define IOU_THR 0.5f
#define SCORE_THR 0.01f
#define KPARTS  49                 // 25088 / 49 = 512
#define KPART_D 512

// ---------------- device scratch ----------------
__device__ float g_WcrT[(size_t)H_DIM * CPAD];            // [h][c]
__device__ float g_Wp[2][(size_t)D_DIM * CPAD];           // fuse partials (h halves)
__device__ float g_Wcr1[(size_t)D_DIM * CPAD];            // [d][c]
__device__ float g_bias[CPAD];
__device__ float g_part[(size_t)KPARTS * M_DIM * CPAD];
__device__ float g_score[M_DIM];
__device__ float g_boxes[M_DIM * 4];

// ---------------- helpers ----------------
__device__ __forceinline__ void fma2(unsigned long long& c, unsigned long long a, unsigned long long b) {
    asm("fma.rn.f32x2 %0, %1, %2, %0;" : "+l"(c) : "l"(a), "l"(b));
}
__device__ __forceinline__ unsigned long long pack2(float lo, float hi) {
    unsigned long long r;
    asm("mov.b64 %0, {%1, %2};" : "=l"(r) : "f"(lo), "f"(hi));
    return r;
}
__device__ __forceinline__ float2 unpack2(unsigned long long v) {
    float2 r;
    asm("mov.b64 {%0, %1}, %2;" : "=f"(r.x), "=f"(r.y) : "l"(v));
    return r;
}
static __device__ __forceinline__ uint32_t smem_u32(const void* p) {
    return (uint32_t)__cvta_generic_to_shared(p);
}
static __device__ __forceinline__ void cp16(uint32_t dst, const void* src) {
    asm volatile("cp.async.cg.shared.global [%0], [%1], 16;" :: "r"(dst), "l"(src) : "memory");
}
static __device__ __forceinline__ void cp_commit() {
    asm volatile("cp.async.commit_group;" ::: "memory");
}
static __device__ __forceinline__ void cp_wait1() {
    asm volatile("cp.async.wait_group 1;" ::: "memory");
}

// ============ prep: WcrT[h][c] ============
__global__ __launch_bounds__(256)
void prep_wcrt(const float* __restrict__ Wc, const float* __restrict__ Wr)
{
    int idx = blockIdx.x * 256 + threadIdx.x;     // 0 .. 131071
    int h = idx >> 5, c = idx & 31;
    float v = 0.f;
    if (c < NCLS)      v = Wc[(size_t)c * H_DIM + h];
    else if (c < 25)   v = Wr[(size_t)(c - NCLS) * H_DIM + h];
    g_WcrT[(size_t)h * CPAD + c] = v;
}

// ============ bias: g_bias[c] = bcr[c] + sum_h Wcr[c][h]*b1[h] ============
__global__ __launch_bounds__(256)
void bias_kernel(const float* __restrict__ Wc, const float* __restrict__ bc,
                 const float* __restrict__ Wr, const float* __restrict__ br,
                 const float* __restrict__ b1)
{
    const int c   = blockIdx.x;
    const int tid = threadIdx.x;
    float s = 0.f;
    if (c < 25) {
        const float* w = (c < NCLS) ? (Wc + (size_t)c * H_DIM) : (Wr + (size_t)(c - NCLS) * H_DIM);
        for (int h = tid; h < H_DIM; h += 256) s += w[h] * b1[h];
    }
    #pragma unroll
    for (int o = 16; o > 0; o >>= 1) s += __shfl_xor_sync(0xffffffffu, s, o);
    __shared__ float part[8];
    if ((tid & 31) == 0) part[tid >> 5] = s;
    __syncthreads();
    if (tid == 0) {
        float t = 0.f;
        #pragma unroll
        for (int w = 0; w < 8; w++) t += part[w];
        float base = (c < NCLS) ? bc[c] : (c < 25 ? br[c - NCLS] : 0.f);
        g_bias[c] = (c < 25) ? (t + base) : 0.f;
    }
}

// ============ fuse_w: Wp[half][d][c] = sum_{h in half} WcrT[h][c] * W1[h][d] ============
// grid (196 d-tiles, 2 halves), 256 thr, 3-stage cp.async. Stage: 32 h x (128 d + 32 c).
#define FW_STAGES 3
#define FW_W1B    16384            // 32*128*4
#define FW_WCB    4096             // 32*32*4
#define FW_STB    (FW_W1B + FW_WCB)
#define FW_SMEM   (FW_STAGES * FW_STB)

static __device__ __forceinline__ void fw_load(uint32_t sb, int tid, int slot,
                                               const float* W1, int h0, int d0) {
    uint32_t sd = sb + (uint32_t)slot * FW_STB;
    // 4 W1 chunks: id = tid + i*256 in [0,1024): row = id>>5 (32 rows), ck = id&31
    #pragma unroll
    for (int i = 0; i < 4; i++) {
        int id = tid + i * 256;
        int r = id >> 5, ck = id & 31;
        cp16(sd + (uint32_t)(r * 512 + ck * 16),
             W1 + (size_t)(h0 + r) * D_DIM + d0 + ck * 4);
    }
    // 1 WcrT chunk: id = tid in [0,256): row = id>>3, ck = id&7
    {
        int r = tid >> 3, ck = tid & 7;
        cp16(sd + FW_W1B + (uint32_t)(r * 128 + ck * 16),
             g_WcrT + (size_t)(h0 + r) * CPAD + ck * 4);
    }
    cp_commit();
}

__global__ __launch_bounds__(256)
void fuse_w(const float* __restrict__ W1)
{
    extern __shared__ char smem[];
    const uint32_t sb = smem_u32(smem);
    const int tid  = threadIdx.x;
    const int d0   = blockIdx.x * 128;
    const int half = blockIdx.y;
    const int hbase = half * (H_DIM / 2);
    const int tx = tid & 31;       // d quad
    const int ty = tid >> 5;       // c quad

    unsigned long long acc2[4][2];
    #pragma unroll
    for (int i = 0; i < 4; i++) { acc2[i][0] = 0ULL; acc2[i][1] = 0ULL; }

    fw_load(sb, tid, 0, W1, hbase, d0);
    fw_load(sb, tid, 1, W1, hbase + 32, d0);

    const int NIT = (H_DIM / 2) / 32;   // 64
    for (int it = 0; it < NIT; it++) {
        cp_wait1();
        __syncthreads();

        const char* s0 = smem + (it % FW_STAGES) * FW_STB;
        const float* Ws = reinterpret_cast<const float*>(s0);              // [k][128]
        const float* Cs = reinterpret_cast<const float*>(s0 + FW_W1B);     // [k][32]

        #pragma unroll
        for (int k = 0; k < 32; k++) {
            float4 b = *reinterpret_cast<const float4*>(Ws + k * 128 + 4 * tx);
            unsigned long long b01 = pack2(b.x, b.y);
            unsigned long long b23 = pack2(b.z, b.w);
            #pragma unroll
            for (int i = 0; i < 4; i++) {
                float a = Cs[k * 32 + 4 * ty + i];
                unsigned long long as = pack2(a, a);
                fma2(acc2[i][0], as, b01);
                fma2(acc2[i][1], as, b23);
            }
        }
        __syncthreads();
        if (it + 2 < NIT) fw_load(sb, tid, (it + 2) % FW_STAGES, W1, hbase + (it + 2) * 32, d0);
        else cp_commit();   // keep group count consistent for wait1
    }

    // transpose-in-registers: float4 along c for each of 4 d
    float va[4][4];
    #pragma unroll
    for (int i = 0; i < 4; i++) {
        float2 p0 = unpack2(acc2[i][0]);
        float2 p1 = unpack2(acc2[i][1]);
        va[0][i] = p0.x; va[1][i] = p0.y; va[2][i] = p1.x; va[3][i] = p1.y;
    }
    float* dst = g_Wp[half];
    #pragma unroll
    for (int j = 0; j < 4; j++) {
        float4 v = make_float4(va[j][0], va[j][1], va[j][2], va[j][3]);
        *reinterpret_cast<float4*>(dst + (size_t)(d0 + 4 * tx + j) * CPAD + 4 * ty) = v;
    }
}

// ============ reduce halves ============
__global__ __launch_bounds__(256)
void reduce_w()
{
    size_t i = ((size_t)blockIdx.x * 256 + threadIdx.x);   // float4 index
    const float4* a = reinterpret_cast<const float4*>(g_Wp[0]);
    const float4* b = reinterpret_cast<const float4*>(g_Wp[1]);
    float4 x = a[i], y = b[i];
    x.x += y.x; x.y += y.y; x.z += y.z; x.w += y.w;
    reinterpret_cast<float4*>(g_Wcr1)[i] = x;
}

// ============ gemm_logits: part[kp][row][c] ============
// grid (16 row-tiles, 49 kparts), 256 thr, 3-stage cp.async. Stage: 128 rows x 32 d + 32x32 w.
#define GL_STAGES 3
#define GL_APITCH 144              // bytes per feats smem row (36 floats)
#define GL_AB     (128 * GL_APITCH) // 18432
#define GL_WB     4096
#define GL_STB    (GL_AB + GL_WB)
#define GL_SMEM   (GL_STAGES * GL_STB)

static __device__ __forceinline__ void gl_load(uint32_t sb, int tid, int slot,
                                               const float* feats, int r0, int d0) {
    uint32_t sd = sb + (uint32_t)slot * GL_STB;
    // 4 feats chunks: id in [0,1024): r = id>>3, ck = id&7
    #pragma unroll
    for (int i = 0; i < 4; i++) {
        int id = tid + i * 256;
        int r = id >> 3, ck = id & 7;
        cp16(sd + (uint32_t)(r * GL_APITCH + ck * 16),
             feats + (size_t)(r0 + r) * D_DIM + d0 + ck * 4);
    }
    // 1 weight chunk
    {
        int r = tid >> 3, ck = tid & 7;
        cp16(sd + GL_AB + (uint32_t)(r * 128 + ck * 16),
             g_Wcr1 + (size_t)(d0 + r) * CPAD + ck * 4);
    }
    cp_commit();
}

__global__ __launch_bounds__(256)
void gemm_logits(const float* __restrict__ feats)
{
    extern __shared__ char smem[];
    const uint32_t sb = smem_u32(smem);
    const int tid = threadIdx.x;
    const int r0  = blockIdx.x * 128;
    const int kp  = blockIdx.y;
    const int dbase = kp * KPART_D;
    const int tx = tid & 7;        // c quad
    const int ty = tid >> 3;       // row quad (0..31)

    unsigned long long acc2[4][2];
    #pragma unroll
    for (int i = 0; i < 4; i++) { acc2[i][0] = 0ULL; acc2[i][1] = 0ULL; }

    gl_load(sb, tid, 0, feats, r0, dbase);
    gl_load(sb, tid, 1, feats, r0, dbase + 32);

    const int NIT = KPART_D / 32;   // 16
    for (int it = 0; it < NIT; it++) {
        cp_wait1();
        __syncthreads();

        const char* s0 = smem + (it % GL_STAGES) * GL_STB;
        const float* As = reinterpret_cast<const float*>(s0);            // [r][36]
        const float* Bs = reinterpret_cast<const float*>(s0 + GL_AB);    // [k][32]

        #pragma unroll
        for (int k = 0; k < 32; k++) {
            float4 b = *reinterpret_cast<const float4*>(Bs + k * 32 + 4 * tx);
            unsigned long long b01 = pack2(b.x, b.y);
            unsigned long long b23 = pack2(b.z, b.w);
            #pragma unroll
            for (int i = 0; i < 4; i++) {
                float a = As[(4 * ty + i) * 36 + k];
                unsigned long long as = pack2(a, a);
                fma2(acc2[i][0], as, b01);
                fma2(acc2[i][1], as, b23);
            }
        }
        __syncthreads();
        if (it + 2 < NIT) gl_load(sb, tid, (it + 2) % GL_STAGES, feats, r0, dbase + (it + 2) * 32);
        else cp_commit();
    }

    #pragma unroll
    for (int i = 0; i < 4; i++) {
        int row = r0 + 4 * ty + i;
        float2 p0 = unpack2(acc2[i][0]);
        float2 p1 = unpack2(acc2[i][1]);
        float4 v = make_float4(p0.x, p0.y, p1.x, p1.y);
        *reinterpret_cast<float4*>(g_part + ((size_t)kp * M_DIM + row) * CPAD + 4 * tx) = v;
    }
}

// ============ decode: reduce partials + softmax/argmax + box decode ============
__global__ __launch_bounds__(256)
void decode_kernel(const float* __restrict__ proposals)
{
    const int warp = threadIdx.x >> 5;
    const int c    = threadIdx.x & 31;
    const int row  = blockIdx.x * 8 + warp;   // 2048 rows / 8 warps

    float logit = g_bias[c];
    #pragma unroll
    for (int kp = 0; kp < KPARTS; kp++)
        logit += g_part[((size_t)kp * M_DIM + row) * CPAD + c];

    float v  = (c < NCLS) ? logit : -INFINITY;
    float m  = v;
    int   am = c;
    #pragma unroll
    for (int o = 16; o > 0; o >>= 1) {
        float mo = __shfl_xor_sync(0xffffffffu, m, o);
        int   ao = __shfl_xor_sync(0xffffffffu, am, o);
        if (mo > m || (mo == m && ao < am)) { m = mo; am = ao; }
    }
    float e = (c < NCLS) ? expf(v - m) : 0.f;
    #pragma unroll
    for (int o = 16; o > 0; o >>= 1) e += __shfl_xor_sync(0xffffffffu, e, o);

    float r0v = __shfl_sync(0xffffffffu, logit, 21);
    float r1v = __shfl_sync(0xffffffffu, logit, 22);
    float r2v = __shfl_sync(0xffffffffu, logit, 23);
    float r3v = __shfl_sync(0xffffffffu, logit, 24);

    if (c == 0) {
        float score = 1.f / e;
        bool valid = (am != 0) && (score >= SCORE_THR);
        g_score[row] = valid ? score : 0.f;
        float p0 = proposals[row * 4 + 0];
        float p1 = proposals[row * 4 + 1];
        float p2 = proposals[row * 4 + 2];
        float p3 = proposals[row * 4 + 3];
        g_boxes[row * 4 + 0] = p0 + p2 * r0v;
        g_boxes[row * 4 + 1] = p1 + p3 * r1v;
        g_boxes[row * 4 + 2] = p2 * expf(r2v);
        g_boxes[row * 4 + 3] = p3 * expf(r3v);
    }
}

// ---------------- NMS (exact jnp semantics) ----------------
__global__ __launch_bounds__(NPROP)
void nms_kernel(float* __restrict__ out)
{
    const int b   = blockIdx.x;
    const int tid = threadIdx.x;

    __shared__ float sx0[NPROP], sy0[NPROP], sx1[NPROP], sy1[NPROP], sarea[NPROP];
    __shared__ float sscore[NPROP];
    __shared__ int   sidx[NPROP];
    __shared__ int   ssupp[NPROP];

    const int gi = b * NPROP + tid;
    float sc = g_score[gi];
    float bx = g_boxes[gi * 4 + 0];
    float by = g_boxes[gi * 4 + 1];
    float bw = g_boxes[gi * 4 + 2];
    float bh = g_boxes[gi * 4 + 3];
    float x0 = fminf(fmaxf(bx, 0.f), IMG_MAX);
    float y0 = fminf(fmaxf(by, 0.f), IMG_MAX);
    float x1 = fminf(fmaxf(bx + bw - 1.f, 0.f), IMG_MAX);
    float y1 = fminf(fmaxf(by + bh - 1.f, 0.f), IMG_MAX);
    sx0[tid] = x0; sy0[tid] = y0; sx1[tid] = x1; sy1[tid] = y1;
    sarea[tid] = fmaxf(x1 - x0 + 1.f, 0.f) * fmaxf(y1 - y0 + 1.f, 0.f);
    sscore[tid] = sc;
    sidx[tid] = tid;
    ssupp[tid] = 0;
    __syncthreads();

    for (int k = 2; k <= NPROP; k <<= 1) {
        for (int j = k >> 1; j > 0; j >>= 1) {
            int ixj = tid ^ j;
            if (ixj > tid) {
                float s1 = sscore[tid], s2 = sscore[ixj];
                int   i1 = sidx[tid],   i2 = sidx[ixj];
                bool aBeforeB = (s1 > s2) || (s1 == s2 && i1 < i2);
                bool up = ((tid & k) == 0);
                if (up ? !aBeforeB : aBeforeB) {
                    sscore[tid] = s2; sscore[ixj] = s1;
                    sidx[tid]   = i2; sidx[ixj]   = i1;
                }
            }
            __syncthreads();
        }
    }

    for (int i = 0; i < NPROP; i++) {
        __syncthreads();
        if (ssupp[i] || !(sscore[i] > 0.f)) continue;
        if (tid == i) continue;
        int pi = sidx[i], pj = sidx[tid];
        float ix0 = fmaxf(sx0[pi], sx0[pj]);
        float iy0 = fmaxf(sy0[pi], sy0[pj]);
        float ix1 = fminf(sx1[pi], sx1[pj]);
        float iy1 = fminf(sy1[pi], sy1[pj]);
        float inter = fmaxf(ix1 - ix0 + 1.f, 0.f) * fmaxf(iy1 - iy0 + 1.f, 0.f);
        float iou = inter / (sarea[pi] + sarea[pj] - inter + 1e-9f);
        if (iou > IOU_THR) ssupp[tid] = 1;
    }
    __syncthreads();

    bool keep = (ssupp[tid] == 0) && (sscore[tid] > 0.f);
    int orig = sidx[tid];
    int g = b * NPROP + orig;
    float osc = keep ? sscore[tid] : 0.f;
    float obx = keep ? g_boxes[g * 4 + 0] : 0.f;
    float oby = keep ? g_boxes[g * 4 + 1] : 0.f;
    float obw = keep ? g_boxes[g * 4 + 2] : 0.f;
    float obh = keep ? g_boxes[g * 4 + 3] : 0.f;
    out[g] = osc;
    float* bbout = out + (size_t)BATCH * NPROP + (size_t)g * 4;
    bbout[0] = obx;
    bbout[1] = oby;
    bbout[2] = obx + obw - 1.f;
    bbout[3] = oby + obh - 1.f;
}

// ---------------- launch ----------------
extern "C" void kernel_launch(void* const* d_in, const int* in_sizes, int n_in,
                              void* d_out, int out_size)
{
    const float* rois      = (const float*)d_in[0];
    const float* proposals = (const float*)d_in[1];
    const float* W1        = (const float*)d_in[2];
    const float* b1        = (const float*)d_in[3];
    const float* Wc        = (const float*)d_in[4];
    const float* bc        = (const float*)d_in[5];
    const float* Wr        = (const float*)d_in[6];
    const float* br        = (const float*)d_in[7];
    float* out = (float*)d_out;

    cudaFuncSetAttribute(fuse_w, cudaFuncAttributeMaxDynamicSharedMemorySize, FW_SMEM);
    cudaFuncSetAttribute(gemm_logits, cudaFuncAttributeMaxDynamicSharedMemorySize, GL_SMEM);

    prep_wcrt<<<(H_DIM * CPAD) / 256, 256>>>(Wc, Wr);
    bias_kernel<<<CPAD, 256>>>(Wc, bc, Wr, br, b1);
    fuse_w<<<dim3(D_DIM / 128, 2), 256, FW_SMEM>>>(W1);
    reduce_w<<<(D_DIM * CPAD / 4) / 256, 256>>>();
    gemm_logits<<<dim3(M_DIM / 128, KPARTS), 256, GL_SMEM>>>(rois);
    decode_kernel<<<M_DIM / 8, 256>>>(proposals);
    nms_kernel<<<BATCH, NPROP>>>(out);
}